// round 2
// baseline (speedup 1.0000x reference)
#include <cuda_runtime.h>
#include <math.h>
#include <stdint.h>

// Problem constants (fixed shapes per reference)
#define BTOK 4096
#define NEXP 8
#define DIN  768
#define DH   2048
#define DOUT 768
#define TOPK 2

// Pair capacity: 8192 pairs + up to 7*127 padding, rounded to 9216 (72 tiles of 128)
#define MAXPAIR 9216
#define MAXMT   72

// ---------------- scratch (device globals; no allocations allowed) ----------------
__device__ float g_h[(size_t)MAXPAIR * DH];    // gelu(x@W1+b1) per pair row
__device__ float g_z[(size_t)MAXPAIR * DOUT];  // h@W2+b2 per pair row
__device__ float g_lse[MAXPAIR];               // logsumexp per pair row
__device__ int   g_pair_token[MAXPAIR];        // token id per pair row (-1 = pad)
__device__ int   g_count[NEXP];
__device__ int   g_cursor[NEXP];
__device__ int   g_off[NEXP + 1];
__device__ int   g_mtile_expert[MAXMT];
__device__ int   g_n_mtiles;
__device__ int   g_tok_e[BTOK * TOPK];
__device__ float g_tok_g[BTOK * TOPK];
__device__ int   g_tok_p[BTOK * TOPK];

// ---------------- init ----------------
__global__ void init_kernel() {
    int i = blockIdx.x * blockDim.x + threadIdx.x;
    if (i < MAXPAIR) g_pair_token[i] = -1;
    if (i < NEXP) { g_count[i] = 0; g_cursor[i] = 0; }
}

// ---------------- gating: fp32 logits, top-2, softmax over kept 2 ----------------
__global__ void gating_kernel(const float* __restrict__ x, const float* __restrict__ wg) {
    int gthread = blockIdx.x * blockDim.x + threadIdx.x;
    int warp = gthread >> 5;
    int lane = gthread & 31;
    if (warp >= BTOK) return;
    const float* xr = x + (size_t)warp * DIN;
    float acc[NEXP];
#pragma unroll
    for (int e = 0; e < NEXP; e++) acc[e] = 0.f;
    for (int i = lane; i < DIN; i += 32) {
        float xv = xr[i];
        const float4* wr = (const float4*)(wg + (size_t)i * NEXP);
        float4 w0 = wr[0], w1 = wr[1];
        acc[0] += xv * w0.x; acc[1] += xv * w0.y; acc[2] += xv * w0.z; acc[3] += xv * w0.w;
        acc[4] += xv * w1.x; acc[5] += xv * w1.y; acc[6] += xv * w1.z; acc[7] += xv * w1.w;
    }
#pragma unroll
    for (int e = 0; e < NEXP; e++)
#pragma unroll
        for (int off = 16; off > 0; off >>= 1)
            acc[e] += __shfl_down_sync(0xFFFFFFFFu, acc[e], off);
    if (lane == 0) {
        // top-2, ties -> lower index (matches jax.lax.top_k)
        float v0 = -3.402823466e38f, v1 = -3.402823466e38f;
        int e0 = 0, e1 = 0;
#pragma unroll
        for (int e = 0; e < NEXP; e++) {
            float v = acc[e];
            if (v > v0) { v1 = v0; e1 = e0; v0 = v; e0 = e; }
            else if (v > v1) { v1 = v; e1 = e; }
        }
        float ex = expf(v1 - v0);        // <= 1
        float inv = 1.0f / (1.0f + ex);
        float gA = inv, gB = ex * inv;   // softmax over [v0, v1]
        g_tok_e[warp * 2 + 0] = e0; g_tok_e[warp * 2 + 1] = e1;
        g_tok_g[warp * 2 + 0] = gA; g_tok_g[warp * 2 + 1] = gB;
        atomicAdd(&g_count[e0], 1);
        atomicAdd(&g_count[e1], 1);
    }
}

// ---------------- offsets: 128-aligned expert segments + tile->expert map ----------------
__global__ void offsets_kernel() {
    if (threadIdx.x != 0 || blockIdx.x != 0) return;
    int off = 0, nt = 0;
    for (int e = 0; e < NEXP; e++) {
        g_off[e] = off;
        int c = g_count[e];
        int tiles = (c + 127) >> 7;
        for (int t = 0; t < tiles; t++) g_mtile_expert[nt + t] = e;
        nt += tiles;
        off += tiles << 7;
    }
    g_off[NEXP] = off;
    g_n_mtiles = nt;
}

// ---------------- assign: token -> pair rows ----------------
__global__ void assign_kernel() {
    int t = blockIdx.x * blockDim.x + threadIdx.x;
    if (t >= BTOK) return;
#pragma unroll
    for (int s = 0; s < TOPK; s++) {
        int e = g_tok_e[t * 2 + s];
        int pos = atomicAdd(&g_cursor[e], 1);
        int p = g_off[e] + pos;
        g_pair_token[p] = t;
        g_tok_p[t * 2 + s] = p;
    }
}

__device__ __forceinline__ float gelu_tanh(float v) {
    // jax.nn.gelu default (approximate=True)
    float v3 = v * v * v;
    return 0.5f * v * (1.0f + tanhf(0.7978845608028654f * (v + 0.044715f * v3)));
}

// ---------------- GEMM1: h = gelu(x[tok] @ W1[e] + b1[e]); M=pairs, N=2048, K=768 ----------------
__global__ __launch_bounds__(256) void gemm1_kernel(const float* __restrict__ x,
                                                    const float* __restrict__ W1,
                                                    const float* __restrict__ b1) {
    int mt = blockIdx.y;
    if (mt >= g_n_mtiles) return;
    int e = g_mtile_expert[mt];
    int row0 = mt << 7;
    int col0 = blockIdx.x << 7;
    const float* Bw = W1 + (size_t)e * DIN * DH;

    __shared__ float As[16][132];
    __shared__ float Bs[16][132];

    int tid = threadIdx.x;
    int tx = tid & 15, ty = tid >> 4;

    float acc[8][8];
#pragma unroll
    for (int i = 0; i < 8; i++)
#pragma unroll
        for (int j = 0; j < 8; j++) acc[i][j] = 0.f;

    int arow = tid >> 1;
    int ak = (tid & 1) * 8;
    int tok = g_pair_token[row0 + arow];
    const float* aptr = (tok >= 0) ? (x + (size_t)tok * DIN + ak) : nullptr;

    int brow = tid >> 5;          // 0..7 (also +8)
    int bcol = (tid & 31) * 4;

    for (int k0 = 0; k0 < DIN; k0 += 16) {
        float4 a0 = make_float4(0.f, 0.f, 0.f, 0.f), a1 = a0;
        if (aptr) {
            a0 = *(const float4*)(aptr + k0);
            a1 = *(const float4*)(aptr + k0 + 4);
        }
        float4 b0 = *(const float4*)(Bw + (size_t)(k0 + brow) * DH + col0 + bcol);
        float4 b1v = *(const float4*)(Bw + (size_t)(k0 + brow + 8) * DH + col0 + bcol);
        As[ak + 0][arow] = a0.x; As[ak + 1][arow] = a0.y;
        As[ak + 2][arow] = a0.z; As[ak + 3][arow] = a0.w;
        As[ak + 4][arow] = a1.x; As[ak + 5][arow] = a1.y;
        As[ak + 6][arow] = a1.z; As[ak + 7][arow] = a1.w;
        *(float4*)&Bs[brow][bcol] = b0;
        *(float4*)&Bs[brow + 8][bcol] = b1v;
        __syncthreads();
#pragma unroll
        for (int kk = 0; kk < 16; kk++) {
            float4 av0 = *(const float4*)&As[kk][ty * 8];
            float4 av1 = *(const float4*)&As[kk][ty * 8 + 4];
            float4 bv0 = *(const float4*)&Bs[kk][tx * 8];
            float4 bv1 = *(const float4*)&Bs[kk][tx * 8 + 4];
            float a[8] = {av0.x, av0.y, av0.z, av0.w, av1.x, av1.y, av1.z, av1.w};
            float b[8] = {bv0.x, bv0.y, bv0.z, bv0.w, bv1.x, bv1.y, bv1.z, bv1.w};
#pragma unroll
            for (int i = 0; i < 8; i++)
#pragma unroll
                for (int j = 0; j < 8; j++) acc[i][j] += a[i] * b[j];
        }
        __syncthreads();
    }

#pragma unroll
    for (int i = 0; i < 8; i++) {
        int r = row0 + ty * 8 + i;
        if (g_pair_token[r] < 0) continue;
        int nb = col0 + tx * 8;
        float4 o0, o1;
        o0.x = gelu_tanh(acc[i][0] + b1[(size_t)e * DH + nb + 0]);
        o0.y = gelu_tanh(acc[i][1] + b1[(size_t)e * DH + nb + 1]);
        o0.z = gelu_tanh(acc[i][2] + b1[(size_t)e * DH + nb + 2]);
        o0.w = gelu_tanh(acc[i][3] + b1[(size_t)e * DH + nb + 3]);
        o1.x = gelu_tanh(acc[i][4] + b1[(size_t)e * DH + nb + 4]);
        o1.y = gelu_tanh(acc[i][5] + b1[(size_t)e * DH + nb + 5]);
        o1.z = gelu_tanh(acc[i][6] + b1[(size_t)e * DH + nb + 6]);
        o1.w = gelu_tanh(acc[i][7] + b1[(size_t)e * DH + nb + 7]);
        *(float4*)&g_h[(size_t)r * DH + nb] = o0;
        *(float4*)&g_h[(size_t)r * DH + nb + 4] = o1;
    }
}

// ---------------- GEMM2: z = h @ W2[e] + b2[e]; M=pairs, N=768, K=2048 ----------------
__global__ __launch_bounds__(256) void gemm2_kernel(const float* __restrict__ W2,
                                                    const float* __restrict__ b2) {
    int mt = blockIdx.y;
    if (mt >= g_n_mtiles) return;
    int e = g_mtile_expert[mt];
    int row0 = mt << 7;
    int col0 = blockIdx.x << 7;
    const float* Bw = W2 + (size_t)e * DH * DOUT;

    __shared__ float As[16][132];
    __shared__ float Bs[16][132];

    int tid = threadIdx.x;
    int tx = tid & 15, ty = tid >> 4;

    float acc[8][8];
#pragma unroll
    for (int i = 0; i < 8; i++)
#pragma unroll
        for (int j = 0; j < 8; j++) acc[i][j] = 0.f;

    int arow = tid >> 1;
    int ak = (tid & 1) * 8;
    const float* aptr = g_h + (size_t)(row0 + arow) * DH + ak;

    int brow = tid >> 5;
    int bcol = (tid & 31) * 4;

    for (int k0 = 0; k0 < DH; k0 += 16) {
        float4 a0 = *(const float4*)(aptr + k0);
        float4 a1 = *(const float4*)(aptr + k0 + 4);
        float4 b0 = *(const float4*)(Bw + (size_t)(k0 + brow) * DOUT + col0 + bcol);
        float4 b1v = *(const float4*)(Bw + (size_t)(k0 + brow + 8) * DOUT + col0 + bcol);
        As[ak + 0][arow] = a0.x; As[ak + 1][arow] = a0.y;
        As[ak + 2][arow] = a0.z; As[ak + 3][arow] = a0.w;
        As[ak + 4][arow] = a1.x; As[ak + 5][arow] = a1.y;
        As[ak + 6][arow] = a1.z; As[ak + 7][arow] = a1.w;
        *(float4*)&Bs[brow][bcol] = b0;
        *(float4*)&Bs[brow + 8][bcol] = b1v;
        __syncthreads();
#pragma unroll
        for (int kk = 0; kk < 16; kk++) {
            float4 av0 = *(const float4*)&As[kk][ty * 8];
            float4 av1 = *(const float4*)&As[kk][ty * 8 + 4];
            float4 bv0 = *(const float4*)&Bs[kk][tx * 8];
            float4 bv1 = *(const float4*)&Bs[kk][tx * 8 + 4];
            float a[8] = {av0.x, av0.y, av0.z, av0.w, av1.x, av1.y, av1.z, av1.w};
            float b[8] = {bv0.x, bv0.y, bv0.z, bv0.w, bv1.x, bv1.y, bv1.z, bv1.w};
#pragma unroll
            for (int i = 0; i < 8; i++)
#pragma unroll
                for (int j = 0; j < 8; j++) acc[i][j] += a[i] * b[j];
        }
        __syncthreads();
    }

#pragma unroll
    for (int i = 0; i < 8; i++) {
        int r = row0 + ty * 8 + i;
        if (g_pair_token[r] < 0) continue;
        int nb = col0 + tx * 8;
        float4 o0, o1;
        o0.x = acc[i][0] + b2[(size_t)e * DOUT + nb + 0];
        o0.y = acc[i][1] + b2[(size_t)e * DOUT + nb + 1];
        o0.z = acc[i][2] + b2[(size_t)e * DOUT + nb + 2];
        o0.w = acc[i][3] + b2[(size_t)e * DOUT + nb + 3];
        o1.x = acc[i][4] + b2[(size_t)e * DOUT + nb + 4];
        o1.y = acc[i][5] + b2[(size_t)e * DOUT + nb + 5];
        o1.z = acc[i][6] + b2[(size_t)e * DOUT + nb + 6];
        o1.w = acc[i][7] + b2[(size_t)e * DOUT + nb + 7];
        *(float4*)&g_z[(size_t)r * DOUT + nb] = o0;
        *(float4*)&g_z[(size_t)r * DOUT + nb + 4] = o1;
    }
}

// ---------------- logsumexp per pair row ----------------
__global__ __launch_bounds__(256) void lse_kernel() {
    int p = blockIdx.x;
    if (g_pair_token[p] < 0) return;
    const float* row = g_z + (size_t)p * DOUT;
    int tid = threadIdx.x;
    __shared__ float sred[256];
    float m = -3.402823466e38f;
#pragma unroll
    for (int i = 0; i < 3; i++) m = fmaxf(m, row[tid + i * 256]);
    sred[tid] = m;
    __syncthreads();
    for (int st = 128; st > 0; st >>= 1) {
        if (tid < st) sred[tid] = fmaxf(sred[tid], sred[tid + st]);
        __syncthreads();
    }
    float rmax = sred[0];
    __syncthreads();
    float s = 0.f;
#pragma unroll
    for (int i = 0; i < 3; i++) s += expf(row[tid + i * 256] - rmax);
    sred[tid] = s;
    __syncthreads();
    for (int st = 128; st > 0; st >>= 1) {
        if (tid < st) sred[tid] += sred[tid + st];
        __syncthreads();
    }
    if (tid == 0) g_lse[p] = rmax + logf(sred[0]);
}

// ---------------- combine: y = log(g0*exp(z0-lse0) + g1*exp(z1-lse1)) ----------------
__global__ __launch_bounds__(256) void combine_kernel(float* __restrict__ out) {
    int b = blockIdx.y;
    int o = blockIdx.x * 256 + threadIdx.x;
    int p0 = g_tok_p[b * 2 + 0], p1 = g_tok_p[b * 2 + 1];
    float g0 = g_tok_g[b * 2 + 0], g1 = g_tok_g[b * 2 + 1];
    float lse0 = g_lse[p0], lse1 = g_lse[p1];
    float z0 = g_z[(size_t)p0 * DOUT + o];
    float z1 = g_z[(size_t)p1 * DOUT + o];
    float c = g0 * expf(z0 - lse0) + g1 * expf(z1 - lse1);
    if (c == 0.0f) c = 2.2204460492503131e-16f;
    out[(size_t)b * DOUT + o] = logf(c);
}

// ---------------- aux loss (deterministic fixed-order reduction) ----------------
__global__ __launch_bounds__(256) void loss_kernel(float* __restrict__ out, int write_loss) {
    __shared__ float simp[NEXP][256];
    int tid = threadIdx.x;
    float imp[NEXP];
#pragma unroll
    for (int e = 0; e < NEXP; e++) imp[e] = 0.f;
    for (int t = tid; t < BTOK; t += 256) {
        imp[g_tok_e[t * 2 + 0]] += g_tok_g[t * 2 + 0];
        imp[g_tok_e[t * 2 + 1]] += g_tok_g[t * 2 + 1];
    }
#pragma unroll
    for (int e = 0; e < NEXP; e++) simp[e][tid] = imp[e];
    __syncthreads();
    for (int st = 128; st > 0; st >>= 1) {
        if (tid < st)
#pragma unroll
            for (int e = 0; e < NEXP; e++) simp[e][tid] += simp[e][tid + st];
        __syncthreads();
    }
    if (tid == 0 && write_loss) {
        float vi[NEXP], vl[NEXP];
        for (int e = 0; e < NEXP; e++) { vi[e] = simp[e][0]; vl[e] = (float)g_cursor[e]; }
        float mi = 0.f, ml = 0.f;
        for (int e = 0; e < NEXP; e++) { mi += vi[e]; ml += vl[e]; }
        mi /= NEXP; ml /= NEXP;
        float si = 0.f, sl = 0.f;
        for (int e = 0; e < NEXP; e++) {
            si += (vi[e] - mi) * (vi[e] - mi);
            sl += (vl[e] - ml) * (vl[e] - ml);
        }
        si /= (NEXP - 1); sl /= (NEXP - 1);  // ddof=1
        float cvi = si / (mi * mi + 1e-10f);
        float cvl = sl / (ml * ml + 1e-10f);
        out[(size_t)BTOK * DOUT] = 0.01f * (cvi + cvl);
    }
}

// ---------------- launch ----------------
extern "C" void kernel_launch(void* const* d_in, const int* in_sizes, int n_in,
                              void* d_out, int out_size) {
    const float* x  = (const float*)d_in[0];  // [B, DIN]
    const float* wg = (const float*)d_in[1];  // [DIN, E]
    const float* W1 = (const float*)d_in[2];  // [E, DIN, DH]
    const float* b1 = (const float*)d_in[3];  // [E, DH]
    const float* W2 = (const float*)d_in[4];  // [E, DH, DOUT]
    const float* b2 = (const float*)d_in[5];  // [E, DOUT]
    float* out = (float*)d_out;

    int write_loss = (out_size > BTOK * DOUT) ? 1 : 0;

    init_kernel<<<(MAXPAIR + 255) / 256, 256>>>();
    gating_kernel<<<(BTOK * 32 + 255) / 256, 256>>>(x, wg);
    offsets_kernel<<<1, 1>>>();
    assign_kernel<<<(BTOK + 255) / 256, 256>>>();
    gemm1_kernel<<<dim3(DH / 128, MAXMT), 256>>>(x, W1, b1);
    gemm2_kernel<<<dim3(DOUT / 128, MAXMT), 256>>>(W2, b2);
    lse_kernel<<<MAXPAIR, 256>>>();
    combine_kernel<<<dim3(DOUT / 256, BTOK), 256>>>(out);
    loss_kernel<<<1, 256>>>(out, write_loss);
}

// round 9
// speedup vs baseline: 1.7320x; 1.7320x over previous
#include <cuda_runtime.h>
#include <cuda_bf16.h>
#include <math.h>
#include <stdint.h>

// Problem constants
#define BTOK 4096
#define NEXP 8
#define DIN  768
#define DH   2048
#define DOUT 768
#define TOPK 2
#define MAXPAIR 9216
#define MAXMT   72

// ---------------- scratch (device globals; SAME footprint class as the passing R2 build) ----------------
__device__ float g_h[(size_t)MAXPAIR * DH];    // gelu(x@W1+b1), fp32
__device__ float g_z[(size_t)MAXPAIR * DOUT];  // h@W2+b2, fp32
__device__ float g_lse[MAXPAIR];
__device__ int   g_pair_token[MAXPAIR];
__device__ int   g_count[NEXP];
__device__ int   g_cursor[NEXP];
__device__ int   g_off[NEXP + 1];
__device__ int   g_mtile_expert[MAXMT];
__device__ int   g_n_mtiles;
__device__ int   g_tok_e[BTOK * TOPK];
__device__ float g_tok_g[BTOK * TOPK];
__device__ int   g_tok_p[BTOK * TOPK];

// ---------------- PTX helpers: ONLY mma.sync + plain shared ld/st ----------------
__device__ __forceinline__ uint32_t smem_u32(const void* p) {
    uint32_t a;
    asm("{ .reg .u64 t; cvta.to.shared.u64 t, %1; cvt.u32.u64 %0, t; }" : "=r"(a) : "l"(p));
    return a;
}
__device__ __forceinline__ uint32_t lds32(uint32_t a) {
    uint32_t v;
    asm volatile("ld.shared.u32 %0, [%1];" : "=r"(v) : "r"(a));
    return v;
}
__device__ __forceinline__ uint32_t lds16(uint32_t a) {
    uint32_t v;
    asm volatile("ld.shared.u16 %0, [%1];" : "=r"(v) : "r"(a));
    return v;
}
__device__ __forceinline__ void sts32(uint32_t a, uint32_t v) {
    asm volatile("st.shared.u32 [%0], %1;" :: "r"(a), "r"(v));
}
__device__ __forceinline__ void mma16816(float& c0, float& c1, float& c2, float& c3,
                                         uint32_t a0, uint32_t a1, uint32_t a2, uint32_t a3,
                                         uint32_t b0, uint32_t b1) {
    asm volatile("mma.sync.aligned.m16n8k16.row.col.f32.bf16.bf16.f32 "
                 "{%0,%1,%2,%3}, {%4,%5,%6,%7}, {%8,%9}, {%0,%1,%2,%3};"
                 : "+f"(c0), "+f"(c1), "+f"(c2), "+f"(c3)
                 : "r"(a0), "r"(a1), "r"(a2), "r"(a3), "r"(b0), "r"(b1));
}

// Shared layout (static, 36.5 KB):
//   A [128 m][rows of 80 B] bf16 hi/lo  (20-word stride -> conflict-free frag lds32)
//   B [32 k][rows of 264 B] bf16 hi/lo
#define A_ROWB 80
#define B_ROWB 264
#define OFF_AH 0
#define OFF_AL 10240
#define OFF_BH 20480
#define OFF_BL 28928
#define SMEM_TOT 37376

// ---------------- small kernels ----------------
__global__ void init_kernel() {
    int i = blockIdx.x * blockDim.x + threadIdx.x;
    if (i < MAXPAIR) g_pair_token[i] = -1;
    if (i < NEXP) { g_count[i] = 0; g_cursor[i] = 0; }
}

__global__ void gating_kernel(const float* __restrict__ x, const float* __restrict__ wg) {
    int gthread = blockIdx.x * blockDim.x + threadIdx.x;
    int warp = gthread >> 5, lane = gthread & 31;
    if (warp >= BTOK) return;
    const float* xr = x + (size_t)warp * DIN;
    float a0 = 0.f, a1 = 0.f, a2 = 0.f, a3 = 0.f, a4 = 0.f, a5 = 0.f, a6 = 0.f, a7 = 0.f;
    for (int i = lane; i < DIN; i += 32) {
        float xv = xr[i];
        const float4* wr = (const float4*)(wg + (size_t)i * NEXP);
        float4 w0 = wr[0], w1 = wr[1];
        a0 += xv * w0.x; a1 += xv * w0.y; a2 += xv * w0.z; a3 += xv * w0.w;
        a4 += xv * w1.x; a5 += xv * w1.y; a6 += xv * w1.z; a7 += xv * w1.w;
    }
#pragma unroll
    for (int off = 16; off > 0; off >>= 1) {
        a0 += __shfl_down_sync(0xFFFFFFFFu, a0, off);
        a1 += __shfl_down_sync(0xFFFFFFFFu, a1, off);
        a2 += __shfl_down_sync(0xFFFFFFFFu, a2, off);
        a3 += __shfl_down_sync(0xFFFFFFFFu, a3, off);
        a4 += __shfl_down_sync(0xFFFFFFFFu, a4, off);
        a5 += __shfl_down_sync(0xFFFFFFFFu, a5, off);
        a6 += __shfl_down_sync(0xFFFFFFFFu, a6, off);
        a7 += __shfl_down_sync(0xFFFFFFFFu, a7, off);
    }
    if (lane == 0) {
        float v0 = -3.402823466e38f, v1 = -3.402823466e38f;
        int e0 = 0, e1 = 0;
#define TOP2(val, idx) { float v = (val); if (v > v0) { v1 = v0; e1 = e0; v0 = v; e0 = idx; } else if (v > v1) { v1 = v; e1 = idx; } }
        TOP2(a0, 0) TOP2(a1, 1) TOP2(a2, 2) TOP2(a3, 3)
        TOP2(a4, 4) TOP2(a5, 5) TOP2(a6, 6) TOP2(a7, 7)
#undef TOP2
        float ex = expf(v1 - v0);
        float inv = 1.0f / (1.0f + ex);
        g_tok_e[warp * 2 + 0] = e0; g_tok_e[warp * 2 + 1] = e1;
        g_tok_g[warp * 2 + 0] = inv; g_tok_g[warp * 2 + 1] = ex * inv;
        atomicAdd(&g_count[e0], 1);
        atomicAdd(&g_count[e1], 1);
    }
}

__global__ void offsets_kernel() {
    if (threadIdx.x != 0 || blockIdx.x != 0) return;
    int off = 0, nt = 0;
    for (int e = 0; e < NEXP; e++) {
        g_off[e] = off;
        int c = g_count[e];
        int tiles = (c + 127) >> 7;
        for (int t = 0; t < tiles; t++) g_mtile_expert[nt + t] = e;
        nt += tiles;
        off += tiles << 7;
    }
    g_off[NEXP] = off;
    g_n_mtiles = nt;
}

__global__ void assign_kernel() {
    int t = blockIdx.x * blockDim.x + threadIdx.x;
    if (t >= BTOK) return;
#pragma unroll
    for (int s = 0; s < TOPK; s++) {
        int e = g_tok_e[t * 2 + s];
        int pos = atomicAdd(&g_cursor[e], 1);
        int p = g_off[e] + pos;
        g_pair_token[p] = t;
        g_tok_p[t * 2 + s] = p;
    }
}

__device__ __forceinline__ float gelu_tanh(float v) {
    float v3 = v * v * v;
    return 0.5f * v * (1.0f + tanhf(0.7978845608028654f * (v + 0.044715f * v3)));
}

// ---------------- grouped GEMM via mma.sync, in-kernel hi/lo bf16 split ----------------
// CTA 128x128, K-chunk 32, single-buffered static smem. 256 threads, 8 warps 2(m)x4(n),
// warp tile 64x32. 3-term split: Ahi*Bhi + Ahi*Blo + Alo*Bhi, fp32 accum.
// ISG1: A = x rows gathered via g_pair_token; out = gelu(acc + b1) -> g_h (fp32).
// else: A = g_h rows; out = acc + b2 -> g_z (fp32).
template<int KTOT, int NBS, bool ISG1>
__global__ __launch_bounds__(256) void gemm_mma(const float* __restrict__ x,
                                                const float* __restrict__ W,
                                                const float* __restrict__ bias) {
    int mt = blockIdx.y;
    if (mt >= g_n_mtiles) return;
    int e = g_mtile_expert[mt];
    int row0 = mt << 7;
    int col0 = blockIdx.x << 7;

    __shared__ __align__(16) unsigned char smem[SMEM_TOT];
    uint32_t sb = smem_u32(smem);
    int tid = threadIdx.x;
    int w = tid >> 5, lane = tid & 31;
    int wm = (w >> 2) * 64;   // 0/64
    int wn = (w & 3) * 32;    // 0/32/64/96

    const float* Wg = W + (size_t)e * KTOT * NBS;

    // A staging coords: thread t covers row=t>>1, k-halfchunk=(t&1)*16
    int arow = tid >> 1, akb = (tid & 1) * 16;
    const float* asrc;
    if (ISG1) {
        int tok = g_pair_token[row0 + arow];
        asrc = (tok >= 0) ? (x + (size_t)tok * KTOT + akb) : nullptr;
    } else {
        asrc = g_h + (size_t)(row0 + arow) * KTOT + akb;
    }
    uint32_t ast = sb + (uint32_t)(arow * A_ROWB + akb * 2);

    // B staging coords: thread t covers k=t>>3, n-seg=(t&7)*16
    int bk = tid >> 3, bnb = (tid & 7) * 16;
    const float* bsrc = Wg + (size_t)bk * NBS + col0 + bnb;
    uint32_t bst = sb + (uint32_t)(bk * B_ROWB + bnb * 2);

#define DECL_ACC(mi, ni) float c##mi##ni##0 = 0.f, c##mi##ni##1 = 0.f, c##mi##ni##2 = 0.f, c##mi##ni##3 = 0.f;
    DECL_ACC(0, 0) DECL_ACC(0, 1) DECL_ACC(0, 2) DECL_ACC(0, 3)
    DECL_ACC(1, 0) DECL_ACC(1, 1) DECL_ACC(1, 2) DECL_ACC(1, 3)
    DECL_ACC(2, 0) DECL_ACC(2, 1) DECL_ACC(2, 2) DECL_ACC(2, 3)
    DECL_ACC(3, 0) DECL_ACC(3, 1) DECL_ACC(3, 2) DECL_ACC(3, 3)
#undef DECL_ACC

    const int NC = KTOT / 32;
    for (int kc = 0; kc < NC; kc++) {
        int k0 = kc * 32;
        // ---- stage A (16 floats) and B (16 floats) with hi/lo split ----
#define SPLIT_STORE(vv, base, joff) do { \
    __nv_bfloat162 h2_ = __floats2bfloat162_rn((vv).x, (vv).y); \
    float2 hf_ = __bfloat1622float2(h2_); \
    __nv_bfloat162 l2_ = __floats2bfloat162_rn((vv).x - hf_.x, (vv).y - hf_.y); \
    sts32((base) + OFF_AH + (joff), *(uint32_t*)&h2_); \
    sts32((base) + OFF_AL + (joff), *(uint32_t*)&l2_); \
} while (0)
#define SPLIT_STOREB(vv, base, joff) do { \
    __nv_bfloat162 h2_ = __floats2bfloat162_rn((vv).x, (vv).y); \
    float2 hf_ = __bfloat1622float2(h2_); \
    __nv_bfloat162 l2_ = __floats2bfloat162_rn((vv).x - hf_.x, (vv).y - hf_.y); \
    sts32((base) + OFF_BH + (joff), *(uint32_t*)&h2_); \
    sts32((base) + OFF_BL + (joff), *(uint32_t*)&l2_); \
} while (0)
        {
            float4 v0, v1, v2, v3;
            if (!ISG1 || asrc) {
                const float4* ap = (const float4*)(asrc + k0);
                v0 = ap[0]; v1 = ap[1]; v2 = ap[2]; v3 = ap[3];
            } else {
                v0 = make_float4(0.f, 0.f, 0.f, 0.f); v1 = v0; v2 = v0; v3 = v0;
            }
            float2 p;
            p = make_float2(v0.x, v0.y); SPLIT_STORE(p, ast, 0);
            p = make_float2(v0.z, v0.w); SPLIT_STORE(p, ast, 4);
            p = make_float2(v1.x, v1.y); SPLIT_STORE(p, ast, 8);
            p = make_float2(v1.z, v1.w); SPLIT_STORE(p, ast, 12);
            p = make_float2(v2.x, v2.y); SPLIT_STORE(p, ast, 16);
            p = make_float2(v2.z, v2.w); SPLIT_STORE(p, ast, 20);
            p = make_float2(v3.x, v3.y); SPLIT_STORE(p, ast, 24);
            p = make_float2(v3.z, v3.w); SPLIT_STORE(p, ast, 28);
        }
        {
            const float4* bp = (const float4*)(bsrc + (size_t)k0 * NBS);
            float4 v0 = bp[0], v1 = bp[1], v2 = bp[2], v3 = bp[3];
            float2 p;
            p = make_float2(v0.x, v0.y); SPLIT_STOREB(p, bst, 0);
            p = make_float2(v0.z, v0.w); SPLIT_STOREB(p, bst, 4);
            p = make_float2(v1.x, v1.y); SPLIT_STOREB(p, bst, 8);
            p = make_float2(v1.z, v1.w); SPLIT_STOREB(p, bst, 12);
            p = make_float2(v2.x, v2.y); SPLIT_STOREB(p, bst, 16);
            p = make_float2(v2.z, v2.w); SPLIT_STOREB(p, bst, 20);
            p = make_float2(v3.x, v3.y); SPLIT_STOREB(p, bst, 24);
            p = make_float2(v3.z, v3.w); SPLIT_STOREB(p, bst, 28);
        }
#undef SPLIT_STORE
#undef SPLIT_STOREB
        __syncthreads();

        // ---- compute: 2 k16 steps ----
#pragma unroll
        for (int ks = 0; ks < 32; ks += 16) {
            int fk = ks + (lane & 3) * 2;           // fragment k base for this lane
            int fn = (lane >> 2);                   // fragment row-in-8
            // B fragments: b = Bs[fk][n] | Bs[fk+1][n]<<16 ; second reg at fk+8
#define LOAD_B(ni, dsth0, dsth1, dstl0, dstl1) do { \
    uint32_t nb_ = sb + (uint32_t)((wn + (ni) * 8 + fn) * 2); \
    uint32_t k0a_ = (uint32_t)(fk * B_ROWB), k1a_ = (uint32_t)((fk + 1) * B_ROWB); \
    uint32_t k8a_ = (uint32_t)((fk + 8) * B_ROWB), k9a_ = (uint32_t)((fk + 9) * B_ROWB); \
    dsth0 = lds16(nb_ + OFF_BH + k0a_) | (lds16(nb_ + OFF_BH + k1a_) << 16); \
    dsth1 = lds16(nb_ + OFF_BH + k8a_) | (lds16(nb_ + OFF_BH + k9a_) << 16); \
    dstl0 = lds16(nb_ + OFF_BL + k0a_) | (lds16(nb_ + OFF_BL + k1a_) << 16); \
    dstl1 = lds16(nb_ + OFF_BL + k8a_) | (lds16(nb_ + OFF_BL + k9a_) << 16); \
} while (0)
            uint32_t bh00, bh01, bl00, bl01; LOAD_B(0, bh00, bh01, bl00, bl01);
            uint32_t bh10, bh11, bl10, bl11; LOAD_B(1, bh10, bh11, bl10, bl11);
            uint32_t bh20, bh21, bl20, bl21; LOAD_B(2, bh20, bh21, bl20, bl21);
            uint32_t bh30, bh31, bl30, bl31; LOAD_B(3, bh30, bh31, bl30, bl31);
#undef LOAD_B

#define DO_MI(mi) do { \
    uint32_t ra_ = sb + (uint32_t)((wm + (mi) * 16 + fn) * A_ROWB + fk * 2); \
    uint32_t rb_ = ra_ + 8 * A_ROWB; \
    uint32_t ah0 = lds32(ra_ + OFF_AH), ah1 = lds32(rb_ + OFF_AH); \
    uint32_t ah2 = lds32(ra_ + OFF_AH + 16), ah3 = lds32(rb_ + OFF_AH + 16); \
    uint32_t al0 = lds32(ra_ + OFF_AL), al1 = lds32(rb_ + OFF_AL); \
    uint32_t al2 = lds32(ra_ + OFF_AL + 16), al3 = lds32(rb_ + OFF_AL + 16); \
    mma16816(c##mi##00, c##mi##01, c##mi##02, c##mi##03, ah0, ah1, ah2, ah3, bh00, bh01); \
    mma16816(c##mi##00, c##mi##01, c##mi##02, c##mi##03, ah0, ah1, ah2, ah3, bl00, bl01); \
    mma16816(c##mi##00, c##mi##01, c##mi##02, c##mi##03, al0, al1, al2, al3, bh00, bh01); \
    mma16816(c##mi##10, c##mi##11, c##mi##12, c##mi##13, ah0, ah1, ah2, ah3, bh10, bh11); \
    mma16816(c##mi##10, c##mi##11, c##mi##12, c##mi##13, ah0, ah1, ah2, ah3, bl10, bl11); \
    mma16816(c##mi##10, c##mi##11, c##mi##12, c##mi##13, al0, al1, al2, al3, bh10, bh11); \
    mma16816(c##mi##20, c##mi##21, c##mi##22, c##mi##23, ah0, ah1, ah2, ah3, bh20, bh21); \
    mma16816(c##mi##20, c##mi##21, c##mi##22, c##mi##23, ah0, ah1, ah2, ah3, bl20, bl21); \
    mma16816(c##mi##20, c##mi##21, c##mi##22, c##mi##23, al0, al1, al2, al3, bh20, bh21); \
    mma16816(c##mi##30, c##mi##31, c##mi##32, c##mi##33, ah0, ah1, ah2, ah3, bh30, bh31); \
    mma16816(c##mi##30, c##mi##31, c##mi##32, c##mi##33, ah0, ah1, ah2, ah3, bl30, bl31); \
    mma16816(c##mi##30, c##mi##31, c##mi##32, c##mi##33, al0, al1, al2, al3, bh30, bh31); \
} while (0)
            DO_MI(0); DO_MI(1); DO_MI(2); DO_MI(3);
#undef DO_MI
        }
        __syncthreads();
    }

    // ---- epilogue: c0,c1 -> (r, gc..gc+1); c2,c3 -> (r+8, ...) ----
    int er = (lane >> 2);
    int ec = (lane & 3) * 2;
#define EPI(mi, ni) do { \
    int r_ = row0 + wm + (mi) * 16 + er; \
    int gc_ = col0 + wn + (ni) * 8 + ec; \
    float bv0 = __ldg(bias + (size_t)e * NBS + gc_); \
    float bv1 = __ldg(bias + (size_t)e * NBS + gc_ + 1); \
    if (ISG1) { \
        float2 o0, o1; \
        o0.x = gelu_tanh(c##mi##ni##0 + bv0); o0.y = gelu_tanh(c##mi##ni##1 + bv1); \
        o1.x = gelu_tanh(c##mi##ni##2 + bv0); o1.y = gelu_tanh(c##mi##ni##3 + bv1); \
        *(float2*)(g_h + (size_t)r_ * NBS + gc_) = o0; \
        *(float2*)(g_h + (size_t)(r_ + 8) * NBS + gc_) = o1; \
    } else { \
        float2 o0, o1; \
        o0.x = c##mi##ni##0 + bv0; o0.y = c##mi##ni##1 + bv1; \
        o1.x = c##mi##ni##2 + bv0; o1.y = c##mi##ni##3 + bv1; \
        *(float2*)(g_z + (size_t)r_ * NBS + gc_) = o0; \
        *(float2*)(g_z + (size_t)(r_ + 8) * NBS + gc_) = o1; \
    } \
} while (0)
    EPI(0, 0); EPI(0, 1); EPI(0, 2); EPI(0, 3);
    EPI(1, 0); EPI(1, 1); EPI(1, 2); EPI(1, 3);
    EPI(2, 0); EPI(2, 1); EPI(2, 2); EPI(2, 3);
    EPI(3, 0); EPI(3, 1); EPI(3, 2); EPI(3, 3);
#undef EPI
}

// ---------------- logsumexp / combine / loss ----------------
__global__ __launch_bounds__(256) void lse_kernel() {
    int p = blockIdx.x;
    if (g_pair_token[p] < 0) return;
    const float* row = g_z + (size_t)p * DOUT;
    int tid = threadIdx.x;
    __shared__ float sred[256];
    float m = fmaxf(fmaxf(row[tid], row[tid + 256]), row[tid + 512]);
    sred[tid] = m;
    __syncthreads();
    for (int st = 128; st > 0; st >>= 1) {
        if (tid < st) sred[tid] = fmaxf(sred[tid], sred[tid + st]);
        __syncthreads();
    }
    float rmax = sred[0];
    __syncthreads();
    float s = expf(row[tid] - rmax) + expf(row[tid + 256] - rmax) + expf(row[tid + 512] - rmax);
    sred[tid] = s;
    __syncthreads();
    for (int st = 128; st > 0; st >>= 1) {
        if (tid < st) sred[tid] += sred[tid + st];
        __syncthreads();
    }
    if (tid == 0) g_lse[p] = rmax + logf(sred[0]);
}

__global__ __launch_bounds__(256) void combine_kernel(float* __restrict__ out) {
    int b = blockIdx.y;
    int o = blockIdx.x * 256 + threadIdx.x;
    int p0 = g_tok_p[b * 2 + 0], p1 = g_tok_p[b * 2 + 1];
    float g0 = g_tok_g[b * 2 + 0], g1 = g_tok_g[b * 2 + 1];
    float lse0 = g_lse[p0], lse1 = g_lse[p1];
    float z0 = g_z[(size_t)p0 * DOUT + o];
    float z1 = g_z[(size_t)p1 * DOUT + o];
    float c = g0 * expf(z0 - lse0) + g1 * expf(z1 - lse1);
    if (c == 0.0f) c = 2.2204460492503131e-16f;
    out[(size_t)b * DOUT + o] = logf(c);
}

// loss: importance sums in shared memory (runtime index never touches local)
__global__ __launch_bounds__(256) void loss_kernel(float* __restrict__ out, int write_loss) {
    __shared__ float simp[NEXP][257];
    int tid = threadIdx.x;
#pragma unroll
    for (int e = 0; e < NEXP; e++) simp[e][tid] = 0.f;
    __syncthreads();
    for (int t = tid; t < BTOK; t += 256) {
        simp[g_tok_e[t * 2 + 0]][tid] += g_tok_g[t * 2 + 0];
        simp[g_tok_e[t * 2 + 1]][tid] += g_tok_g[t * 2 + 1];
    }
    __syncthreads();
    for (int st = 128; st > 0; st >>= 1) {
        if (tid < st)
#pragma unroll
            for (int e = 0; e < NEXP; e++) simp[e][tid] += simp[e][tid + st];
        __syncthreads();
    }
    if (tid == 0 && write_loss) {
        float mi = 0.f, ml = 0.f;
        for (int e = 0; e < NEXP; e++) { mi += simp[e][0]; ml += (float)g_cursor[e]; }
        mi /= NEXP; ml /= NEXP;
        float si = 0.f, sl = 0.f;
        for (int e = 0; e < NEXP; e++) {
            float di = simp[e][0] - mi;
            float dl = (float)g_cursor[e] - ml;
            si += di * di;
            sl += dl * dl;
        }
        si /= (NEXP - 1); sl /= (NEXP - 1);
        out[(size_t)BTOK * DOUT] = 0.01f * (si / (mi * mi + 1e-10f) + sl / (ml * ml + 1e-10f));
    }
}

// ---------------- launch ----------------
extern "C" void kernel_launch(void* const* d_in, const int* in_sizes, int n_in,
                              void* d_out, int out_size) {
    const float* x  = (const float*)d_in[0];
    const float* wg = (const float*)d_in[1];
    const float* W1 = (const float*)d_in[2];
    const float* b1 = (const float*)d_in[3];
    const float* W2 = (const float*)d_in[4];
    const float* b2 = (const float*)d_in[5];
    float* out = (float*)d_out;

    int write_loss = (out_size > BTOK * DOUT) ? 1 : 0;

    init_kernel<<<(MAXPAIR + 255) / 256, 256>>>();
    gating_kernel<<<(BTOK * 32 + 255) / 256, 256>>>(x, wg);
    offsets_kernel<<<1, 1>>>();
    assign_kernel<<<(BTOK + 255) / 256, 256>>>();
    gemm_mma<DIN, DH, true><<<dim3(DH / 128, MAXMT), 256>>>(x, W1, b1);
    gemm_mma<DH, DOUT, false><<<dim3(DOUT / 128, MAXMT), 256>>>(x, W2, b2);
    lse_kernel<<<MAXPAIR, 256>>>();
    combine_kernel<<<dim3(DOUT / 256, BTOK), 256>>>(out);
    loss_kernel<<<1, 256>>>(out, write_loss);
}

// round 11
// speedup vs baseline: 2.3351x; 1.3482x over previous
#include <cuda_runtime.h>
#include <cuda_bf16.h>
#include <math.h>
#include <stdint.h>

// Problem constants
#define BTOK 4096
#define NEXP 8
#define DIN  768
#define DH   2048
#define DOUT 768
#define TOPK 2
#define MAXPAIR 9216
#define MAXMT   72
#define K16_1 48    // DIN/16
#define K16_2 128   // DH/16

// ---------------- device globals: TOTAL must stay < 128 MiB (driver granule) ----------------
// A2 fragments (hi/lo): 36 MiB + 36 MiB
__device__ uint4 g_a2fh[(size_t)(MAXPAIR / 16) * K16_2 * 32];
__device__ uint4 g_a2fl[(size_t)(MAXPAIR / 16) * K16_2 * 32];
// Union region (27 MiB): A1 fragments (hi @0, lo @A1F_BYTES) during GEMM1; z fp32 afterwards.
#define A1F_BYTES 14155776  // (MAXPAIR/16) * K16_1 * 32 * 16
__device__ __align__(16) unsigned char g_union[(size_t)MAXPAIR * DOUT * 4];  // 28,311,552 B
__device__ float g_lse[MAXPAIR];
__device__ int   g_pair_token[MAXPAIR];
__device__ int   g_count[NEXP];
__device__ int   g_cursor[NEXP];
__device__ int   g_off[NEXP + 1];
__device__ int   g_mtile_expert[MAXMT];
__device__ int   g_n_mtiles;
__device__ int   g_tok_e[BTOK * TOPK];
__device__ float g_tok_g[BTOK * TOPK];
__device__ int   g_tok_p[BTOK * TOPK];

// ---------------- PTX helpers (NO cp.async, NO ldmatrix, NO dynamic smem) ----------------
__device__ __forceinline__ uint32_t smem_u32(const void* p) {
    uint32_t a;
    asm("{ .reg .u64 t; cvta.to.shared.u64 t, %1; cvt.u32.u64 %0, t; }" : "=r"(a) : "l"(p));
    return a;
}
__device__ __forceinline__ void lds128v(uint4& v, uint32_t a) {
    asm volatile("ld.shared.v4.u32 {%0,%1,%2,%3}, [%4];"
                 : "=r"(v.x), "=r"(v.y), "=r"(v.z), "=r"(v.w) : "r"(a));
}
__device__ __forceinline__ void lds64v(uint2& v, uint32_t a) {
    asm volatile("ld.shared.v2.u32 {%0,%1}, [%2];" : "=r"(v.x), "=r"(v.y) : "r"(a));
}
__device__ __forceinline__ void sts128v(uint32_t a, uint4 v) {
    asm volatile("st.shared.v4.u32 [%0], {%1,%2,%3,%4};"
                 :: "r"(a), "r"(v.x), "r"(v.y), "r"(v.z), "r"(v.w));
}
__device__ __forceinline__ void sts32(uint32_t a, uint32_t v) {
    asm volatile("st.shared.u32 [%0], %1;" :: "r"(a), "r"(v));
}
__device__ __forceinline__ void mma16816(float& c0, float& c1, float& c2, float& c3,
                                         uint32_t a0, uint32_t a1, uint32_t a2, uint32_t a3,
                                         uint32_t b0, uint32_t b1) {
    asm volatile("mma.sync.aligned.m16n8k16.row.col.f32.bf16.bf16.f32 "
                 "{%0,%1,%2,%3}, {%4,%5,%6,%7}, {%8,%9}, {%0,%1,%2,%3};"
                 : "+f"(c0), "+f"(c1), "+f"(c2), "+f"(c3)
                 : "r"(a0), "r"(a1), "r"(a2), "r"(a3), "r"(b0), "r"(b1));
}
__device__ __forceinline__ void hilo(float a, float b, uint32_t& h, uint32_t& l) {
    __nv_bfloat162 hh = __floats2bfloat162_rn(a, b);
    float2 hf = __bfloat1622float2(hh);
    __nv_bfloat162 ll = __floats2bfloat162_rn(a - hf.x, b - hf.y);
    h = *(uint32_t*)&hh;
    l = *(uint32_t*)&ll;
}
__device__ __forceinline__ float gelu_tanh(float v) {
    float v3 = v * v * v;
    return 0.5f * v * (1.0f + tanhf(0.7978845608028654f * (v + 0.044715f * v3)));
}

// smem layout (static 33,280 B): A-hi 8K | A-lo 8K | B-hi 8448 | B-lo 8448
#define AHI 0
#define ALO 8192
#define BHI 16384
#define BLO 24832
#define B_TILE_STRIDE 264   // n8 tile stride (256B data + 8B pad -> bank spread)
#define B_J_STRIDE 4224     // 16 tiles per k16-sub

// ---------------- small kernels ----------------
__global__ void init_kernel() {
    int i = blockIdx.x * blockDim.x + threadIdx.x;
    if (i < MAXPAIR) g_pair_token[i] = -1;
    if (i < NEXP) { g_count[i] = 0; g_cursor[i] = 0; }
}

__global__ void gating_kernel(const float* __restrict__ x, const float* __restrict__ wg) {
    int gthread = blockIdx.x * blockDim.x + threadIdx.x;
    int warp = gthread >> 5, lane = gthread & 31;
    if (warp >= BTOK) return;
    const float* xr = x + (size_t)warp * DIN;
    float a0 = 0.f, a1 = 0.f, a2 = 0.f, a3 = 0.f, a4 = 0.f, a5 = 0.f, a6 = 0.f, a7 = 0.f;
    for (int i = lane; i < DIN; i += 32) {
        float xv = xr[i];
        const float4* wr = (const float4*)(wg + (size_t)i * NEXP);
        float4 w0 = wr[0], w1 = wr[1];
        a0 += xv * w0.x; a1 += xv * w0.y; a2 += xv * w0.z; a3 += xv * w0.w;
        a4 += xv * w1.x; a5 += xv * w1.y; a6 += xv * w1.z; a7 += xv * w1.w;
    }
#pragma unroll
    for (int off = 16; off > 0; off >>= 1) {
        a0 += __shfl_down_sync(0xFFFFFFFFu, a0, off);
        a1 += __shfl_down_sync(0xFFFFFFFFu, a1, off);
        a2 += __shfl_down_sync(0xFFFFFFFFu, a2, off);
        a3 += __shfl_down_sync(0xFFFFFFFFu, a3, off);
        a4 += __shfl_down_sync(0xFFFFFFFFu, a4, off);
        a5 += __shfl_down_sync(0xFFFFFFFFu, a5, off);
        a6 += __shfl_down_sync(0xFFFFFFFFu, a6, off);
        a7 += __shfl_down_sync(0xFFFFFFFFu, a7, off);
    }
    if (lane == 0) {
        float v0 = -3.402823466e38f, v1 = -3.402823466e38f;
        int e0 = 0, e1 = 0;
#define TOP2(val, idx) { float v = (val); if (v > v0) { v1 = v0; e1 = e0; v0 = v; e0 = idx; } else if (v > v1) { v1 = v; e1 = idx; } }
        TOP2(a0, 0) TOP2(a1, 1) TOP2(a2, 2) TOP2(a3, 3)
        TOP2(a4, 4) TOP2(a5, 5) TOP2(a6, 6) TOP2(a7, 7)
#undef TOP2
        float ex = expf(v1 - v0);
        float inv = 1.0f / (1.0f + ex);
        g_tok_e[warp * 2 + 0] = e0; g_tok_e[warp * 2 + 1] = e1;
        g_tok_g[warp * 2 + 0] = inv; g_tok_g[warp * 2 + 1] = ex * inv;
        atomicAdd(&g_count[e0], 1);
        atomicAdd(&g_count[e1], 1);
    }
}

__global__ void offsets_kernel() {
    if (threadIdx.x != 0 || blockIdx.x != 0) return;
    int off = 0, nt = 0;
    for (int e = 0; e < NEXP; e++) {
        g_off[e] = off;
        int c = g_count[e];
        int tiles = (c + 127) >> 7;
        for (int t = 0; t < tiles; t++) g_mtile_expert[nt + t] = e;
        nt += tiles;
        off += tiles << 7;
    }
    g_off[NEXP] = off;
    g_n_mtiles = nt;
}

__global__ void assign_kernel() {
    int t = blockIdx.x * blockDim.x + threadIdx.x;
    if (t >= BTOK) return;
#pragma unroll
    for (int s = 0; s < TOPK; s++) {
        int e = g_tok_e[t * 2 + s];
        int pos = atomicAdd(&g_cursor[e], 1);
        int p = g_off[e] + pos;
        g_pair_token[p] = t;
        g_tok_p[t * 2 + s] = p;
    }
}

// ---------------- gather_x: pair rows -> A1 fragments (hi/lo) in g_union ----------------
__global__ __launch_bounds__(256) void gather_x(const float* __restrict__ x) {
    __shared__ float s[16][260];
    uint4* a1fh = (uint4*)g_union;
    uint4* a1fl = (uint4*)(g_union + A1F_BYTES);
    int bt = blockIdx.x;  // m16 tile 0..575
    int t = threadIdx.x;
    int wi = t >> 5, lane = t & 31;
    int fr = lane >> 2, fk = (lane & 3) * 2;
    for (int c = 0; c < 3; c++) {
#pragma unroll
        for (int r = 0; r < 16; r++) {
            int tok = g_pair_token[bt * 16 + r];
            s[r][t] = (tok >= 0) ? x[(size_t)tok * DIN + c * 256 + t] : 0.f;
        }
        __syncthreads();
#pragma unroll
        for (int sub = 0; sub < 2; sub++) {
            int ktl = wi * 2 + sub;
            int kb = ktl * 16;
            uint4 H, L;
            hilo(s[fr][kb + fk], s[fr][kb + fk + 1], H.x, L.x);
            hilo(s[fr + 8][kb + fk], s[fr + 8][kb + fk + 1], H.y, L.y);
            hilo(s[fr][kb + fk + 8], s[fr][kb + fk + 9], H.z, L.z);
            hilo(s[fr + 8][kb + fk + 8], s[fr + 8][kb + fk + 9], H.w, L.w);
            size_t ad = ((size_t)bt * K16_1 + c * 16 + ktl) * 32 + lane;
            a1fh[ad] = H;
            a1fl[ad] = L;
        }
        __syncthreads();
    }
}

// ---------------- GEMM: pre-fragmented A + in-kernel-converted B, reg-prefetch pipelined ----------------
// CTA 128x128, 256 thr, 8 warps 2(m)x4(n), warp tile 64x32, K-chunk 32 (2 k16 steps).
template<int K16T, int NB, bool ISG1>
__global__ __launch_bounds__(256) void gemm_frag(const float* __restrict__ W,
                                                 const float* __restrict__ bias) {
    int mt = blockIdx.y;
    if (mt >= g_n_mtiles) return;
    int e = g_mtile_expert[mt];
    int col0 = blockIdx.x << 7;

    __shared__ __align__(16) unsigned char sm[33280];
    uint32_t sb = smem_u32(sm);
    int tid = threadIdx.x, w = tid >> 5, lane = tid & 31;
    int wm16 = (w >> 2) * 4;   // m16 sub-tile base (0/4)
    int wn = (w & 3) * 32;
    int wn8 = (w & 3) * 4;     // n8 sub-tile base

    const uint4* Afh = ISG1 ? (const uint4*)g_union : g_a2fh;
    const uint4* Afl = ISG1 ? (const uint4*)(g_union + A1F_BYTES) : g_a2fl;
    float* zp = (float*)g_union;

    // A staging: thread -> (m16 tile ai = tid>>5, lane), copies both k16 subs per chunk
    int ai = tid >> 5;
    size_t aB = ((size_t)(mt * 8 + ai) * K16T) * 32 + (tid & 31);
    uint32_t dA0 = sb + AHI + (uint32_t)((ai * 2 + 0) * 512 + (tid & 31) * 16);
    uint32_t dA1 = dA0 + 512;

    // B staging: thread -> k-pair kp = (tid>>4)*2, n8 seg = tid&15 (8 n's)
    int kp = (tid >> 4) * 2;
    int nseg8 = tid & 15;
    int j_b = kp >> 4;
    int rem = kp & 15;
    uint32_t comp = (rem >= 8) ? 4u : 0u;
    int lq = (rem & 7) >> 1;
    uint32_t bst_hi = sb + BHI + (uint32_t)(j_b * B_J_STRIDE + nseg8 * B_TILE_STRIDE + lq * 8) + comp;
    uint32_t bst_lo = bst_hi + (BLO - BHI);
    const float* bw = W + ((size_t)e * (K16T * 16) + kp) * NB + col0 + nseg8 * 8;

    // compute-phase bases
    uint32_t aF = sb + AHI + (uint32_t)(lane * 16);
    uint32_t bF = sb + BHI + (uint32_t)(lane * 8);

#define DECL_ACC(mi, ni) float c##mi##ni##0 = 0.f, c##mi##ni##1 = 0.f, c##mi##ni##2 = 0.f, c##mi##ni##3 = 0.f;
    DECL_ACC(0, 0) DECL_ACC(0, 1) DECL_ACC(0, 2) DECL_ACC(0, 3)
    DECL_ACC(1, 0) DECL_ACC(1, 1) DECL_ACC(1, 2) DECL_ACC(1, 3)
    DECL_ACC(2, 0) DECL_ACC(2, 1) DECL_ACC(2, 2) DECL_ACC(2, 3)
    DECL_ACC(3, 0) DECL_ACC(3, 1) DECL_ACC(3, 2) DECL_ACC(3, 3)
#undef DECL_ACC

    uint4 pah0, pah1, pal0, pal1;
    float4 pb00, pb01, pb10, pb11;
#define PREFETCH(ck) do { \
    pah0 = Afh[aB + ((ck) * 2 + 0) * 32]; pah1 = Afh[aB + ((ck) * 2 + 1) * 32]; \
    pal0 = Afl[aB + ((ck) * 2 + 0) * 32]; pal1 = Afl[aB + ((ck) * 2 + 1) * 32]; \
    const float* p_ = bw + (size_t)(ck) * 32 * NB; \
    pb00 = *(const float4*)(p_);          pb01 = *(const float4*)(p_ + 4); \
    pb10 = *(const float4*)(p_ + NB);     pb11 = *(const float4*)(p_ + NB + 4); \
} while (0)
#define BSTS(i, va, vb) do { \
    uint32_t h_, l_; hilo(va, vb, h_, l_); \
    sts32(bst_hi + (i) * 32, h_); sts32(bst_lo + (i) * 32, l_); \
} while (0)
#define STAGE() do { \
    sts128v(dA0, pah0); sts128v(dA1, pah1); \
    sts128v(dA0 + 8192, pal0); sts128v(dA1 + 8192, pal1); \
    BSTS(0, pb00.x, pb10.x); BSTS(1, pb00.y, pb10.y); \
    BSTS(2, pb00.z, pb10.z); BSTS(3, pb00.w, pb10.w); \
    BSTS(4, pb01.x, pb11.x); BSTS(5, pb01.y, pb11.y); \
    BSTS(6, pb01.z, pb11.z); BSTS(7, pb01.w, pb11.w); \
} while (0)
#define MMA3(mi, ni) \
    mma16816(c##mi##ni##0, c##mi##ni##1, c##mi##ni##2, c##mi##ni##3, \
             ah##mi.x, ah##mi.y, ah##mi.z, ah##mi.w, bh##ni.x, bh##ni.y); \
    mma16816(c##mi##ni##0, c##mi##ni##1, c##mi##ni##2, c##mi##ni##3, \
             ah##mi.x, ah##mi.y, ah##mi.z, ah##mi.w, bl##ni.x, bl##ni.y); \
    mma16816(c##mi##ni##0, c##mi##ni##1, c##mi##ni##2, c##mi##ni##3, \
             al##mi.x, al##mi.y, al##mi.z, al##mi.w, bh##ni.x, bh##ni.y);
#define COMPUTE_J(j) do { \
    uint4 ah0, ah1, ah2, ah3, al0, al1, al2, al3; \
    uint2 bh0, bh1, bh2, bh3, bl0, bl1, bl2, bl3; \
    lds128v(ah0, aF + ((wm16 + 0) * 2 + (j)) * 512); \
    lds128v(ah1, aF + ((wm16 + 1) * 2 + (j)) * 512); \
    lds128v(ah2, aF + ((wm16 + 2) * 2 + (j)) * 512); \
    lds128v(ah3, aF + ((wm16 + 3) * 2 + (j)) * 512); \
    lds128v(al0, aF + 8192 + ((wm16 + 0) * 2 + (j)) * 512); \
    lds128v(al1, aF + 8192 + ((wm16 + 1) * 2 + (j)) * 512); \
    lds128v(al2, aF + 8192 + ((wm16 + 2) * 2 + (j)) * 512); \
    lds128v(al3, aF + 8192 + ((wm16 + 3) * 2 + (j)) * 512); \
    lds64v(bh0, bF + (j) * B_J_STRIDE + (wn8 + 0) * B_TILE_STRIDE); \
    lds64v(bh1, bF + (j) * B_J_STRIDE + (wn8 + 1) * B_TILE_STRIDE); \
    lds64v(bh2, bF + (j) * B_J_STRIDE + (wn8 + 2) * B_TILE_STRIDE); \
    lds64v(bh3, bF + (j) * B_J_STRIDE + (wn8 + 3) * B_TILE_STRIDE); \
    lds64v(bl0, bF + (BLO - BHI) + (j) * B_J_STRIDE + (wn8 + 0) * B_TILE_STRIDE); \
    lds64v(bl1, bF + (BLO - BHI) + (j) * B_J_STRIDE + (wn8 + 1) * B_TILE_STRIDE); \
    lds64v(bl2, bF + (BLO - BHI) + (j) * B_J_STRIDE + (wn8 + 2) * B_TILE_STRIDE); \
    lds64v(bl3, bF + (BLO - BHI) + (j) * B_J_STRIDE + (wn8 + 3) * B_TILE_STRIDE); \
    MMA3(0, 0) MMA3(0, 1) MMA3(0, 2) MMA3(0, 3) \
    MMA3(1, 0) MMA3(1, 1) MMA3(1, 2) MMA3(1, 3) \
    MMA3(2, 0) MMA3(2, 1) MMA3(2, 2) MMA3(2, 3) \
    MMA3(3, 0) MMA3(3, 1) MMA3(3, 2) MMA3(3, 3) \
} while (0)

    const int NC = K16T / 2;
    PREFETCH(0);
    for (int ck = 0; ck < NC; ck++) {
        STAGE();
        __syncthreads();
        if (ck + 1 < NC) PREFETCH(ck + 1);
        COMPUTE_J(0);
        COMPUTE_J(1);
        __syncthreads();
    }
#undef PREFETCH
#undef BSTS
#undef STAGE
#undef COMPUTE_J
#undef MMA3

    // ---- epilogue ----
    int er = lane >> 2;
    int ec = (lane & 3) * 2;
#define EPI(mi) do { \
    if (ISG1) { \
        size_t m16o = (size_t)(mt * 8 + wm16 + (mi)); \
        int gc0 = col0 + wn + ec; \
        { \
            float bE0 = __ldg(bias + (size_t)e * DH + gc0); \
            float bE1 = __ldg(bias + (size_t)e * DH + gc0 + 1); \
            float bO0 = __ldg(bias + (size_t)e * DH + gc0 + 8); \
            float bO1 = __ldg(bias + (size_t)e * DH + gc0 + 9); \
            uint4 H, L; \
            hilo(gelu_tanh(c##mi##00 + bE0), gelu_tanh(c##mi##01 + bE1), H.x, L.x); \
            hilo(gelu_tanh(c##mi##02 + bE0), gelu_tanh(c##mi##03 + bE1), H.y, L.y); \
            hilo(gelu_tanh(c##mi##10 + bO0), gelu_tanh(c##mi##11 + bO1), H.z, L.z); \
            hilo(gelu_tanh(c##mi##12 + bO0), gelu_tanh(c##mi##13 + bO1), H.w, L.w); \
            size_t ad = (m16o * K16_2 + (size_t)((col0 + wn) >> 4)) * 32 + lane; \
            g_a2fh[ad] = H; g_a2fl[ad] = L; \
        } \
        { \
            float bE0 = __ldg(bias + (size_t)e * DH + gc0 + 16); \
            float bE1 = __ldg(bias + (size_t)e * DH + gc0 + 17); \
            float bO0 = __ldg(bias + (size_t)e * DH + gc0 + 24); \
            float bO1 = __ldg(bias + (size_t)e * DH + gc0 + 25); \
            uint4 H, L; \
            hilo(gelu_tanh(c##mi##20 + bE0), gelu_tanh(c##mi##21 + bE1), H.x, L.x); \
            hilo(gelu_tanh(c##mi##22 + bE0), gelu_tanh(c##mi##23 + bE1), H.y, L.y); \
            hilo(gelu_tanh(c##mi##30 + bO0), gelu_tanh(c##mi##31 + bO1), H.z, L.z); \
            hilo(gelu_tanh(c##mi##32 + bO0), gelu_tanh(c##mi##33 + bO1), H.w, L.w); \
            size_t ad = (m16o * K16_2 + (size_t)(((col0 + wn) >> 4) + 1)) * 32 + lane; \
            g_a2fh[ad] = H; g_a2fl[ad] = L; \
        } \
    } else { \
        int rb = mt * 128 + (wm16 + (mi)) * 16 + er; \
        int gcb = col0 + wn + ec; \
        float b0v = __ldg(bias + (size_t)e * DOUT + gcb); \
        float b1v = __ldg(bias + (size_t)e * DOUT + gcb + 1); \
        float b8v = __ldg(bias + (size_t)e * DOUT + gcb + 8); \
        float b9v = __ldg(bias + (size_t)e * DOUT + gcb + 9); \
        float b16v = __ldg(bias + (size_t)e * DOUT + gcb + 16); \
        float b17v = __ldg(bias + (size_t)e * DOUT + gcb + 17); \
        float b24v = __ldg(bias + (size_t)e * DOUT + gcb + 24); \
        float b25v = __ldg(bias + (size_t)e * DOUT + gcb + 25); \
        float2 o; \
        o.x = c##mi##00 + b0v;  o.y = c##mi##01 + b1v;  *(float2*)(zp + (size_t)rb * DOUT + gcb) = o; \
        o.x = c##mi##02 + b0v;  o.y = c##mi##03 + b1v;  *(float2*)(zp + (size_t)(rb + 8) * DOUT + gcb) = o; \
        o.x = c##mi##10 + b8v;  o.y = c##mi##11 + b9v;  *(float2*)(zp + (size_t)rb * DOUT + gcb + 8) = o; \
        o.x = c##mi##12 + b8v;  o.y = c##mi##13 + b9v;  *(float2*)(zp + (size_t)(rb + 8) * DOUT + gcb + 8) = o; \
        o.x = c##mi##20 + b16v; o.y = c##mi##21 + b17v; *(float2*)(zp + (size_t)rb * DOUT + gcb + 16) = o; \
        o.x = c##mi##22 + b16v; o.y = c##mi##23 + b17v; *(float2*)(zp + (size_t)(rb + 8) * DOUT + gcb + 16) = o; \
        o.x = c##mi##30 + b24v; o.y = c##mi##31 + b25v; *(float2*)(zp + (size_t)rb * DOUT + gcb + 24) = o; \
        o.x = c##mi##32 + b24v; o.y = c##mi##33 + b25v; *(float2*)(zp + (size_t)(rb + 8) * DOUT + gcb + 24) = o; \
    } \
} while (0)
    EPI(0); EPI(1); EPI(2); EPI(3);
#undef EPI
}

// ---------------- logsumexp / combine / loss (z lives in g_union) ----------------
__global__ __launch_bounds__(256) void lse_kernel() {
    int p = blockIdx.x;
    if (g_pair_token[p] < 0) return;
    const float* row = (const float*)g_union + (size_t)p * DOUT;
    int tid = threadIdx.x;
    __shared__ float sred[256];
    float m = fmaxf(fmaxf(row[tid], row[tid + 256]), row[tid + 512]);
    sred[tid] = m;
    __syncthreads();
    for (int st = 128; st > 0; st >>= 1) {
        if (tid < st) sred[tid] = fmaxf(sred[tid], sred[tid + st]);
        __syncthreads();
    }
    float rmax = sred[0];
    __syncthreads();
    float s = expf(row[tid] - rmax) + expf(row[tid + 256] - rmax) + expf(row[tid + 512] - rmax);
    sred[tid] = s;
    __syncthreads();
    for (int st = 128; st > 0; st >>= 1) {
        if (tid < st) sred[tid] += sred[tid + st];
        __syncthreads();
    }
    if (tid == 0) g_lse[p] = rmax + logf(sred[0]);
}

__global__ __launch_bounds__(256) void combine_kernel(float* __restrict__ out) {
    const float* zp = (const float*)g_union;
    int b = blockIdx.y;
    int o = blockIdx.x * 256 + threadIdx.x;
    int p0 = g_tok_p[b * 2 + 0], p1 = g_tok_p[b * 2 + 1];
    float g0 = g_tok_g[b * 2 + 0], g1 = g_tok_g[b * 2 + 1];
    float lse0 = g_lse[p0], lse1 = g_lse[p1];
    float z0 = zp[(size_t)p0 * DOUT + o];
    float z1 = zp[(size_t)p1 * DOUT + o];
    float c = g0 * expf(z0 - lse0) + g1 * expf(z1 - lse1);
    if (c == 0.0f) c = 2.2204460492503131e-16f;
    out[(size_t)b * DOUT + o] = logf(c);
}

__global__ __launch_bounds__(256) void loss_kernel(float* __restrict__ out, int write_loss) {
    __shared__ float simp[NEXP][257];
    int tid = threadIdx.x;
#pragma unroll
    for (int e = 0; e < NEXP; e++) simp[e][tid] = 0.f;
    __syncthreads();
    for (int t = tid; t < BTOK; t += 256) {
        simp[g_tok_e[t * 2 + 0]][tid] += g_tok_g[t * 2 + 0];
        simp[g_tok_e[t * 2 + 1]][tid] += g_tok_g[t * 2 + 1];
    }
    __syncthreads();
    for (int st = 128; st > 0; st >>= 1) {
        if (tid < st)
#pragma unroll
            for (int e = 0; e < NEXP; e++) simp[e][tid] += simp[e][tid + st];
        __syncthreads();
    }
    if (tid == 0 && write_loss) {
        float mi = 0.f, ml = 0.f;
        for (int e = 0; e < NEXP; e++) { mi += simp[e][0]; ml += (float)g_cursor[e]; }
        mi /= NEXP; ml /= NEXP;
        float si = 0.f, sl = 0.f;
        for (int e = 0; e < NEXP; e++) {
            float di = simp[e][0] - mi;
            float dl = (float)g_cursor[e] - ml;
            si += di * di;
            sl += dl * dl;
        }
        si /= (NEXP - 1); sl /= (NEXP - 1);
        out[(size_t)BTOK * DOUT] = 0.01f * (si / (mi * mi + 1e-10f) + sl / (ml * ml + 1e-10f));
    }
}

// ---------------- launch ----------------
extern "C" void kernel_launch(void* const* d_in, const int* in_sizes, int n_in,
                              void* d_out, int out_size) {
    const float* x  = (const float*)d_in[0];
    const float* wg = (const float*)d_in[1];
    const float* W1 = (const float*)d_in[2];
    const float* b1 = (const float*)d_in[3];
    const float* W2 = (const float*)d_in[4];
    const float* b2 = (const float*)d_in[5];
    float* out = (float*)d_out;

    int write_loss = (out_size > BTOK * DOUT) ? 1 : 0;

    init_kernel<<<(MAXPAIR + 255) / 256, 256>>>();
    gating_kernel<<<(BTOK * 32 + 255) / 256, 256>>>(x, wg);
    offsets_kernel<<<1, 1>>>();
    assign_kernel<<<(BTOK + 255) / 256, 256>>>();
    gather_x<<<MAXPAIR / 16, 256>>>(x);
    gemm_frag<K16_1, DH, true><<<dim3(DH / 128, MAXMT), 256>>>(W1, b1);
    gemm_frag<K16_2, DOUT, false><<<dim3(DOUT / 128, MAXMT), 256>>>(W2, b2);
    lse_kernel<<<MAXPAIR, 256>>>();
    combine_kernel<<<dim3(DOUT / 256, BTOK), 256>>>(out);
    loss_kernel<<<1, 256>>>(out, write_loss);
}